// round 14
// baseline (speedup 1.0000x reference)
#include <cuda_runtime.h>
#include <cuda_bf16.h>
#include <cuda_fp16.h>
#include <cstdint>

#define NT      8192
#define THRESH  0.7f
#define NCH     64          // i-chunks per CTA
#define TI      128         // i per chunk
#define RS      72          // V/U/P smem row stride in 16-bit elems (144 B)
#define RSE     136         // E smem row stride in 16-bit elems (272 B)

// ---------------- device scratch (__device__ globals; no allocs) ----------------
__device__ float  g_eff[NT * 128];        // gated states fp32 [task][c]
__device__ float  g_diag[NT];             // sigmoid(u_j . v_j + b)
__device__ __half g_Uh[NT * 64], g_Ul[NT * 64];   // U fp16 hi/lo split
__device__ __half g_Vf[NT * 64];                  // V fp16 (single plane)
__device__ __half g_ET[128 * NT];                 // Eff^T [c][i] fp16

// ---------------- helpers ----------------
__device__ __forceinline__ uint32_t s2u(const void* p) {
    uint32_t a;
    asm("{ .reg .u64 t; cvta.to.shared.u64 t, %1; cvt.u32.u64 %0, t; }" : "=r"(a) : "l"(p));
    return a;
}
__device__ __forceinline__ void cpasync16(uint32_t dst, const void* src) {
    asm volatile("cp.async.cg.shared.global [%0], [%1], 16;" :: "r"(dst), "l"(src));
}
#define CP_COMMIT() asm volatile("cp.async.commit_group;")
#define CP_WAIT0()  asm volatile("cp.async.wait_group 0;" ::: "memory")

__device__ __forceinline__ void ldsm4(uint32_t* r, uint32_t addr) {
    asm volatile("ldmatrix.sync.aligned.m8n8.x4.shared.b16 {%0,%1,%2,%3}, [%4];"
        : "=r"(r[0]), "=r"(r[1]), "=r"(r[2]), "=r"(r[3]) : "r"(addr));
}
__device__ __forceinline__ void ldsm4t(uint32_t* r, uint32_t addr) {
    asm volatile("ldmatrix.sync.aligned.m8n8.x4.trans.shared.b16 {%0,%1,%2,%3}, [%4];"
        : "=r"(r[0]), "=r"(r[1]), "=r"(r[2]), "=r"(r[3]) : "r"(addr));
}
__device__ __forceinline__ void mma_f16(float* c, const uint32_t* a, const uint32_t* b) {
    asm volatile("mma.sync.aligned.m16n8k16.row.col.f32.f16.f16.f32 "
        "{%0,%1,%2,%3}, {%4,%5,%6,%7}, {%8,%9}, {%0,%1,%2,%3};"
        : "+f"(c[0]), "+f"(c[1]), "+f"(c[2]), "+f"(c[3])
        : "r"(a[0]), "r"(a[1]), "r"(a[2]), "r"(a[3]), "r"(b[0]), "r"(b[1]));
}
__device__ __forceinline__ uint32_t f16x2_of(float lo, float hi) {
    uint32_t r; asm("cvt.rn.f16x2.f32 %0, %1, %2;" : "=r"(r) : "f"(hi), "f"(lo)); return r;
}
// sigmoid(x) = 0.5 + 0.5*tanh(x/2)  — single HW MUFU op
__device__ __forceinline__ float sigm(float x) {
    float t; asm("tanh.approx.f32 %0, %1;" : "=f"(t) : "f"(0.5f * x));
    return fmaf(0.5f, t, 0.5f);
}

// ---------------- SMEM layout (bytes) ----------------
#define O_UH 0                    // 64 x 144
#define O_UL 9216
#define O_V  18432                // + (k%3)*18432   (3 bufs, 128 rows x 144B fp16)
#define O_E  73728                // + (k%3)*34816   (3 bufs, 128 rows x 272B)
#define O_P  178176               // + (k&1)*18432   (2 bufs, 128 rows x 144B)
#define SMEM_TOTAL 215040

// ============================================================================
// prep: per 64-row block — V=U@W (fp32) -> fp16, U fp16 hi/lo, diag, eff, ET
// ============================================================================
#define PREP_SMEM ((4096 + 64*65 + 128*64) * 4)
__global__ void __launch_bounds__(256) prep_kernel(const float* __restrict__ states,
                                                   const float* __restrict__ prof,
                                                   const float* __restrict__ U,
                                                   const float* __restrict__ W,
                                                   const float* __restrict__ bptr) {
    extern __shared__ float sm[];
    float* sW = sm;                    // [64][64]
    float* sU = sm + 4096;             // [64][65]
    float* sT = sm + 4096 + 64 * 65;   // [128 c][64 ii]
    const int tid = threadIdx.x;
    const int r0 = blockIdx.x * 64;
    const float bias = __ldg(bptr);

    for (int i = tid; i < 4096; i += 256) sW[i] = W[i];
    for (int i = tid; i < 4096; i += 256) {
        int r = i >> 6, e = i & 63;
        sU[r * 65 + e] = U[(r0 + r) * 64 + e];
    }
    for (int t = tid; t < 2048; t += 256) {
        int b = t >> 10, rem = t & 1023, ii = rem >> 4, d4 = rem & 15;
        int i = r0 + ii;
        float g = prof[b * NT + i] - THRESH;
        g = g > 0.0f ? g : 0.0f;
        float4 s4 = *(const float4*)&states[(b * NT + i) * 64 + d4 * 4];
        int c = b * 64 + d4 * 4;
        sT[(c + 0) * 64 + ii] = s4.x * g;
        sT[(c + 1) * 64 + ii] = s4.y * g;
        sT[(c + 2) * 64 + ii] = s4.z * g;
        sT[(c + 3) * 64 + ii] = s4.w * g;
        float4 e4; e4.x = s4.x * g; e4.y = s4.y * g; e4.z = s4.z * g; e4.w = s4.w * g;
        *(float4*)&g_eff[i * 128 + c] = e4;
    }
    __syncthreads();

    // V rows (fp32 accumulate), then fp16 store
    const int row = tid >> 2, f0 = (tid & 3) * 16;
    float acc[16];
    #pragma unroll
    for (int q = 0; q < 16; q++) acc[q] = 0.0f;
    #pragma unroll 8
    for (int e = 0; e < 64; e++) {
        float u = sU[row * 65 + e];
        #pragma unroll
        for (int q4 = 0; q4 < 4; q4++) {
            float4 wv = *(const float4*)&sW[e * 64 + f0 + q4 * 4];
            acc[q4 * 4 + 0] += u * wv.x; acc[q4 * 4 + 1] += u * wv.y;
            acc[q4 * 4 + 2] += u * wv.z; acc[q4 * 4 + 3] += u * wv.w;
        }
    }
    const int base = (r0 + row) * 64 + f0;
    #pragma unroll
    for (int q = 0; q < 16; q += 2)
        *(uint32_t*)((__half*)g_Vf + base + q) = f16x2_of(acc[q], acc[q + 1]);

    // diag: quad-reduce u.v (fp32 path)
    float s = 0.0f;
    #pragma unroll
    for (int q = 0; q < 16; q++) s += acc[q] * sU[row * 65 + f0 + q];
    s += __shfl_xor_sync(0xffffffffu, s, 1);
    s += __shfl_xor_sync(0xffffffffu, s, 2);
    if ((tid & 3) == 0) g_diag[r0 + row] = sigm(s + bias);

    // U fp16 hi/lo splits
    for (int i = tid; i < 2048; i += 256) {
        int rr = i >> 5, ep = (i & 31) * 2;
        float u0 = sU[rr * 65 + ep], u1 = sU[rr * 65 + ep + 1];
        __half a0 = __float2half_rn(u0), a1 = __float2half_rn(u1);
        float l0 = u0 - __half2float(a0), l1 = u1 - __half2float(a1);
        int gi = (r0 + rr) * 64 + ep;
        *(__half2*)((__half*)g_Uh + gi) = __halves2half2(a0, a1);
        *(__half2*)((__half*)g_Ul + gi) = __halves2half2(__float2half_rn(l0), __float2half_rn(l1));
    }
    // ET fp16
    for (int t = tid; t < 4096; t += 256) {
        int c = t >> 5, ii = (t & 31) * 2;
        __half2 h2 = __floats2half2_rn(sT[c * 64 + ii], sT[c * 64 + ii + 1]);
        *(__half2*)((__half*)g_ET + (size_t)c * NT + r0 + ii) = h2;
    }
}

// ============================================================================
// chunk prefetch: V (128x64 fp16) + ET (128x128 fp16), buffers k%3
// ============================================================================
__device__ __forceinline__ void load_chunk(uint32_t sb, int k, int tid) {
    const int buf = k % 3;
    const int i0 = k * TI;
    const uint32_t vd = sb + O_V + buf * 18432;
    #pragma unroll
    for (int r = 0; r < 2; r++) {
        int id = r * 512 + tid;                      // 0..1023
        int row = id >> 3, q = id & 7;
        const __half* src = g_Vf + (i0 + row) * 64 + q * 8;
        cpasync16(vd + row * (RS * 2) + q * 16, src);
    }
    const uint32_t ed = sb + O_E + buf * 34816;
    #pragma unroll
    for (int r = 0; r < 4; r++) {
        int id = r * 512 + tid;                      // 0..2047
        int row = id >> 4, q = id & 15;
        const __half* src = g_ET + (size_t)row * NT + i0 + q * 8;
        cpasync16(ed + row * (RSE * 2) + q * 16, src);
    }
}

// ============================================================================
// main: 128 CTAs x 64-j tile, 512 threads.
// ONE barrier per chunk: GEMM1(k) -> sigmoid -> P[k&1] -> CP_WAIT0 -> barrier
//   -> prefetch(k+2) -> GEMM2(k).  V/E 3-deep rings, P 2-deep.
// ============================================================================
__global__ void __launch_bounds__(512, 1) main_kernel(const float* __restrict__ states,
                                                      const float* __restrict__ bptr,
                                                      float* __restrict__ out) {
    extern __shared__ char smem[];
    const uint32_t sb = s2u(smem);
    const int tid = threadIdx.x, w = tid >> 5, lane = tid & 31;
    const int jb = blockIdx.x * 64;
    const float bias = __ldg(bptr);

    const int lm = lane >> 3, lr = lane & 7;
    const int aRow = lr + (lm & 1) * 8;
    const int aCol = (lm >> 1) * 8;
    const int bRow = lr + (lm >> 1) * 8;
    const int bCol = (lm & 1) * 8;

    const int i0w = (w >> 1) * 16;     // GEMM1: 16i x 32j per warp (8 x 2 grid)
    const int jn0 = (w & 1) * 32;
    const int j0w = (w >> 2) * 16;     // GEMM2: 16j x 32c per warp (4 x 4 grid)
    const int c0w = (w & 3) * 32;

    // ---- persistent U tile (2 fp16 planes) + chunks 0,1 ----
    #pragma unroll
    for (int r = 0; r < 2; r++) {
        int id = r * 512 + tid;                      // 0..1023
        int pl = id >> 9, rem = id & 511, row = rem >> 3, q = rem & 7;
        const __half* src = (pl ? g_Ul : g_Uh) + (jb + row) * 64 + q * 8;
        cpasync16(sb + (pl ? O_UL : O_UH) + row * (RS * 2) + q * 16, src);
    }
    load_chunk(sb, 0, tid);
    load_chunk(sb, 1, tid);
    CP_COMMIT();
    CP_WAIT0();
    __syncthreads();

    float cacc[4][4];
    #pragma unroll
    for (int q = 0; q < 4; q++)
        #pragma unroll
        for (int v = 0; v < 4; v++) cacc[q][v] = 0.0f;

    for (int k = 0; k < NCH; k++) {
        const int vbuf = k % 3;
        const int pbuf = k & 1;

        // ---- GEMM1: S[16i x 32j] = V . U^T  (2 passes: V.Uh, V.Ul) ----
        const uint32_t vbase = sb + O_V + vbuf * 18432;
        uint32_t VF[4][4];
        #pragma unroll
        for (int kk = 0; kk < 4; kk++)
            ldsm4(VF[kk], vbase + ((i0w + aRow) * RS + kk * 16 + aCol) * 2);

        float sacc[4][4];
        #pragma unroll
        for (int q = 0; q < 4; q++)
            #pragma unroll
            for (int v = 0; v < 4; v++) sacc[q][v] = 0.0f;

        #pragma unroll
        for (int kk = 0; kk < 4; kk++) {
            uint32_t uh0[4], uh1[4];
            ldsm4(uh0, sb + O_UH + ((jn0 + bRow) * RS + kk * 16 + bCol) * 2);
            ldsm4(uh1, sb + O_UH + ((jn0 + 16 + bRow) * RS + kk * 16 + bCol) * 2);
            mma_f16(sacc[0], VF[kk], uh0); mma_f16(sacc[1], VF[kk], uh0 + 2);
            mma_f16(sacc[2], VF[kk], uh1); mma_f16(sacc[3], VF[kk], uh1 + 2);
            uint32_t ul0[4], ul1[4];
            ldsm4(ul0, sb + O_UL + ((jn0 + bRow) * RS + kk * 16 + bCol) * 2);
            ldsm4(ul1, sb + O_UL + ((jn0 + 16 + bRow) * RS + kk * 16 + bCol) * 2);
            mma_f16(sacc[0], VF[kk], ul0); mma_f16(sacc[1], VF[kk], ul0 + 2);
            mma_f16(sacc[2], VF[kk], ul1); mma_f16(sacc[3], VF[kk], ul1 + 2);
        }

        // ---- sigmoid -> P[k&1] fp16 ----
        {
            const int pr = i0w + (lane >> 2);
            const int pc = jn0 + (lane & 3) * 2;
            char* pbase = smem + O_P + pbuf * 18432;
            #pragma unroll
            for (int nt = 0; nt < 4; nt++) {
                float s0 = sigm(sacc[nt][0] + bias);
                float s1 = sigm(sacc[nt][1] + bias);
                float s2 = sigm(sacc[nt][2] + bias);
                float s3 = sigm(sacc[nt][3] + bias);
                char* ph = pbase + (pr * RS + pc + nt * 8) * 2;
                *(uint32_t*)ph = f16x2_of(s0, s1);
                *(uint32_t*)(ph + 8 * RS * 2) = f16x2_of(s2, s3);
            }
        }

        CP_WAIT0();          // chunk k+1 resident (this thread's copies)
        __syncthreads();     // publish P[k&1] + chunk k+1; all GEMM2(k-1) done

        // prefetch chunk k+2 into ring slot (k+2)%3 (safe: last read at k-1)
        if (k + 2 < NCH) { load_chunk(sb, k + 2, tid); CP_COMMIT(); }

        // ---- GEMM2: C[16j x 32c] += P^T . ET  (fp16, K=128) ----
        {
            const uint32_t pbase = sb + O_P + pbuf * 18432;
            const uint32_t ebase = sb + O_E + vbuf * 34816;
            #pragma unroll
            for (int kk = 0; kk < 8; kk++) {
                uint32_t a[4];
                ldsm4t(a, pbase + ((kk * 16 + bRow) * RS + j0w + bCol) * 2);
                #pragma unroll
                for (int ct = 0; ct < 2; ct++) {
                    uint32_t b[4];
                    ldsm4(b, ebase + ((c0w + ct * 16 + bRow) * RSE + kk * 16 + bCol) * 2);
                    mma_f16(cacc[ct * 2],     a, b);
                    mma_f16(cacc[ct * 2 + 1], a, b + 2);
                }
            }
        }
    }

    // ---- epilogue: out = states + C - diag*eff ----
    {
        const int jrb = jb + j0w + (lane >> 2);
        const int ccb = (lane & 3) * 2;
        #pragma unroll
        for (int h = 0; h < 2; h++) {
            const int j = jrb + h * 8;
            const float dg = g_diag[j];
            #pragma unroll
            for (int q = 0; q < 4; q++) {
                const int c = c0w + q * 8 + ccb;
                const int b = c >> 6, d = c & 63;
                const int idx = (b * NT + j) * 64 + d;
                float2 st = *(const float2*)&states[idx];
                float2 ef = *(const float2*)&g_eff[j * 128 + c];
                float2 o;
                o.x = st.x + cacc[q][h * 2]     - dg * ef.x;
                o.y = st.y + cacc[q][h * 2 + 1] - dg * ef.y;
                *(float2*)&out[idx] = o;
            }
        }
    }
}

// ============================================================================
extern "C" void kernel_launch(void* const* d_in, const int* in_sizes, int n_in,
                              void* d_out, int out_size) {
    const float* states = (const float*)d_in[0];  // [2,8192,64]
    const float* prof   = (const float*)d_in[1];  // [2,8192]
    const float* U      = (const float*)d_in[2];  // [8192,64]
    const float* W      = (const float*)d_in[3];  // [1,64,64]
    const float* bias   = (const float*)d_in[4];  // [1]
    float* out = (float*)d_out;

    cudaFuncSetAttribute(prep_kernel, cudaFuncAttributeMaxDynamicSharedMemorySize, PREP_SMEM);
    prep_kernel<<<NT / 64, 256, PREP_SMEM>>>(states, prof, U, W, bias);

    cudaFuncSetAttribute(main_kernel, cudaFuncAttributeMaxDynamicSharedMemorySize, SMEM_TOTAL);
    main_kernel<<<NT / 64, 512, SMEM_TOTAL>>>(states, bias, out);
}

// round 15
// speedup vs baseline: 1.2454x; 1.2454x over previous
#include <cuda_runtime.h>
#include <cuda_bf16.h>
#include <cuda_fp16.h>
#include <cstdint>

#define NT      8192
#define THRESH  0.7f
#define NCH     64          // i-chunks per CTA
#define TI      128         // i per chunk
#define RS      72          // U/V smem row stride in 16-bit elems (144 B)
#define RSE     136         // E smem row stride in 16-bit elems (272 B)

// ---------------- device scratch (__device__ globals; no allocs) ----------------
__device__ float  g_eff[NT * 128];        // gated states fp32 [task][c]
__device__ float  g_diag[NT];             // sigmoid(u_j . v_j + b)
__device__ __half g_Uh[NT * 64], g_Ul[NT * 64];   // U fp16 hi/lo split
__device__ __half g_Vf[NT * 64];                  // V fp16 (single plane)
__device__ __half g_ET[128 * NT];                 // Eff^T [c][i] fp16

// ---------------- helpers ----------------
__device__ __forceinline__ uint32_t s2u(const void* p) {
    uint32_t a;
    asm("{ .reg .u64 t; cvta.to.shared.u64 t, %1; cvt.u32.u64 %0, t; }" : "=r"(a) : "l"(p));
    return a;
}
__device__ __forceinline__ void cpasync16(uint32_t dst, const void* src) {
    asm volatile("cp.async.cg.shared.global [%0], [%1], 16;" :: "r"(dst), "l"(src));
}
#define CP_COMMIT() asm volatile("cp.async.commit_group;")
#define CP_WAIT0()  asm volatile("cp.async.wait_group 0;" ::: "memory")
#define CP_WAIT1()  asm volatile("cp.async.wait_group 1;" ::: "memory")

__device__ __forceinline__ void ldsm4(uint32_t* r, uint32_t addr) {
    asm volatile("ldmatrix.sync.aligned.m8n8.x4.shared.b16 {%0,%1,%2,%3}, [%4];"
        : "=r"(r[0]), "=r"(r[1]), "=r"(r[2]), "=r"(r[3]) : "r"(addr));
}
__device__ __forceinline__ void mma_f16(float* c, const uint32_t* a, const uint32_t* b) {
    asm volatile("mma.sync.aligned.m16n8k16.row.col.f32.f16.f16.f32 "
        "{%0,%1,%2,%3}, {%4,%5,%6,%7}, {%8,%9}, {%0,%1,%2,%3};"
        : "+f"(c[0]), "+f"(c[1]), "+f"(c[2]), "+f"(c[3])
        : "r"(a[0]), "r"(a[1]), "r"(a[2]), "r"(a[3]), "r"(b[0]), "r"(b[1]));
}
__device__ __forceinline__ uint32_t f16x2_of(float lo, float hi) {
    uint32_t r; asm("cvt.rn.f16x2.f32 %0, %1, %2;" : "=r"(r) : "f"(hi), "f"(lo)); return r;
}
// sigmoid(x) = 0.5 + 0.5*tanh(x/2)  — single HW MUFU op
__device__ __forceinline__ float sigm(float x) {
    float t; asm("tanh.approx.f32 %0, %1;" : "=f"(t) : "f"(0.5f * x));
    return fmaf(0.5f, t, 0.5f);
}

// ---------------- SMEM layout (bytes) ----------------
#define O_UH 0                    // 64 x 144
#define O_UL 9216
#define O_V  18432                // + (k%3)*18432   (3 bufs, 128 rows x 144B fp16)
#define O_E  73728                // + (k%3)*34816   (3 bufs, 128 rows x 272B)
#define SMEM_TOTAL 178176         // epilogue reduction reuses [0, 128K)

// ============================================================================
// prep: per 64-row block — V=U@W (fp32) -> fp16, U fp16 hi/lo, diag, eff, ET
// ============================================================================
#define PREP_SMEM ((4096 + 64*65 + 128*64) * 4)
__global__ void __launch_bounds__(256) prep_kernel(const float* __restrict__ states,
                                                   const float* __restrict__ prof,
                                                   const float* __restrict__ U,
                                                   const float* __restrict__ W,
                                                   const float* __restrict__ bptr) {
    extern __shared__ float sm[];
    float* sW = sm;                    // [64][64]
    float* sU = sm + 4096;             // [64][65]
    float* sT = sm + 4096 + 64 * 65;   // [128 c][64 ii]
    const int tid = threadIdx.x;
    const int r0 = blockIdx.x * 64;
    const float bias = __ldg(bptr);

    for (int i = tid; i < 4096; i += 256) sW[i] = W[i];
    for (int i = tid; i < 4096; i += 256) {
        int r = i >> 6, e = i & 63;
        sU[r * 65 + e] = U[(r0 + r) * 64 + e];
    }
    for (int t = tid; t < 2048; t += 256) {
        int b = t >> 10, rem = t & 1023, ii = rem >> 4, d4 = rem & 15;
        int i = r0 + ii;
        float g = prof[b * NT + i] - THRESH;
        g = g > 0.0f ? g : 0.0f;
        float4 s4 = *(const float4*)&states[(b * NT + i) * 64 + d4 * 4];
        int c = b * 64 + d4 * 4;
        sT[(c + 0) * 64 + ii] = s4.x * g;
        sT[(c + 1) * 64 + ii] = s4.y * g;
        sT[(c + 2) * 64 + ii] = s4.z * g;
        sT[(c + 3) * 64 + ii] = s4.w * g;
        float4 e4; e4.x = s4.x * g; e4.y = s4.y * g; e4.z = s4.z * g; e4.w = s4.w * g;
        *(float4*)&g_eff[i * 128 + c] = e4;
    }
    __syncthreads();

    // V rows (fp32 accumulate), then fp16 store
    const int row = tid >> 2, f0 = (tid & 3) * 16;
    float acc[16];
    #pragma unroll
    for (int q = 0; q < 16; q++) acc[q] = 0.0f;
    #pragma unroll 8
    for (int e = 0; e < 64; e++) {
        float u = sU[row * 65 + e];
        #pragma unroll
        for (int q4 = 0; q4 < 4; q4++) {
            float4 wv = *(const float4*)&sW[e * 64 + f0 + q4 * 4];
            acc[q4 * 4 + 0] += u * wv.x; acc[q4 * 4 + 1] += u * wv.y;
            acc[q4 * 4 + 2] += u * wv.z; acc[q4 * 4 + 3] += u * wv.w;
        }
    }
    const int base = (r0 + row) * 64 + f0;
    #pragma unroll
    for (int q = 0; q < 16; q += 2)
        *(uint32_t*)((__half*)g_Vf + base + q) = f16x2_of(acc[q], acc[q + 1]);

    // diag: quad-reduce u.v (fp32 path)
    float s = 0.0f;
    #pragma unroll
    for (int q = 0; q < 16; q++) s += acc[q] * sU[row * 65 + f0 + q];
    s += __shfl_xor_sync(0xffffffffu, s, 1);
    s += __shfl_xor_sync(0xffffffffu, s, 2);
    if ((tid & 3) == 0) g_diag[r0 + row] = sigm(s + bias);

    // U fp16 hi/lo splits
    for (int i = tid; i < 2048; i += 256) {
        int rr = i >> 5, ep = (i & 31) * 2;
        float u0 = sU[rr * 65 + ep], u1 = sU[rr * 65 + ep + 1];
        __half a0 = __float2half_rn(u0), a1 = __float2half_rn(u1);
        float l0 = u0 - __half2float(a0), l1 = u1 - __half2float(a1);
        int gi = (r0 + rr) * 64 + ep;
        *(__half2*)((__half*)g_Uh + gi) = __halves2half2(a0, a1);
        *(__half2*)((__half*)g_Ul + gi) = __halves2half2(__float2half_rn(l0), __float2half_rn(l1));
    }
    // ET fp16
    for (int t = tid; t < 4096; t += 256) {
        int c = t >> 5, ii = (t & 31) * 2;
        __half2 h2 = __floats2half2_rn(sT[c * 64 + ii], sT[c * 64 + ii + 1]);
        *(__half2*)((__half*)g_ET + (size_t)c * NT + r0 + ii) = h2;
    }
}

// ============================================================================
// chunk prefetch: V (128x64 fp16) + ET (128x128 fp16), ring slot k%3
// ============================================================================
__device__ __forceinline__ void load_chunk(uint32_t sb, int k, int tid) {
    const int buf = k % 3;
    const int i0 = k * TI;
    const uint32_t vd = sb + O_V + buf * 18432;
    #pragma unroll
    for (int r = 0; r < 2; r++) {
        int id = r * 512 + tid;                      // 0..1023
        int row = id >> 3, q = id & 7;
        const __half* src = g_Vf + (i0 + row) * 64 + q * 8;
        cpasync16(vd + row * (RS * 2) + q * 16, src);
    }
    const uint32_t ed = sb + O_E + buf * 34816;
    #pragma unroll
    for (int r = 0; r < 4; r++) {
        int id = r * 512 + tid;                      // 0..2047
        int row = id >> 4, q = id & 15;
        const __half* src = g_ET + (size_t)row * NT + i0 + q * 8;
        cpasync16(ed + row * (RSE * 2) + q * 16, src);
    }
}

// ============================================================================
// main: 128 CTAs x 64-j tile, 512 threads = 16 warps (jg 0..3 x ig 0..3).
// GEMM1 computes S^T[16j x 32i] per warp (A=U, B=V); sigmoid + pack to
// GEMM2 A-fragments IN REGISTERS (no P smem round trip); GEMM2 accumulates
// C[16j x 128c] over the warp's 32-i K-slice across all chunks; 4-way ig
// reduction once at the end.  One barrier per chunk (ring reuse only).
// ============================================================================
__global__ void __launch_bounds__(512, 1) main_kernel(const float* __restrict__ states,
                                                      const float* __restrict__ bptr,
                                                      float* __restrict__ out) {
    extern __shared__ char smem[];
    const uint32_t sb = s2u(smem);
    const int tid = threadIdx.x, w = tid >> 5, lane = tid & 31;
    const int jb = blockIdx.x * 64;
    const float bias = __ldg(bptr);

    const int lm = lane >> 3, lr = lane & 7;
    const int aRow = lr + (lm & 1) * 8;
    const int aCol = (lm >> 1) * 8;
    const int bRow = lr + (lm >> 1) * 8;
    const int bCol = (lm & 1) * 8;

    const int jg = w >> 2, ig = w & 3;
    const int j0 = jg * 16;            // j rows within tile (GEMM1 A, GEMM2 M)
    const int i0 = ig * 32;            // i cols within chunk (GEMM1 B, GEMM2 K)

    // ---- persistent U tile (2 fp16 planes) + chunks 0,1 ----
    #pragma unroll
    for (int r = 0; r < 2; r++) {
        int id = r * 512 + tid;                      // 0..1023
        int pl = id >> 9, rem = id & 511, row = rem >> 3, q = rem & 7;
        const __half* src = (pl ? g_Ul : g_Uh) + (jb + row) * 64 + q * 8;
        cpasync16(sb + (pl ? O_UL : O_UH) + row * (RS * 2) + q * 16, src);
    }
    load_chunk(sb, 0, tid);
    CP_COMMIT();
    load_chunk(sb, 1, tid);
    CP_COMMIT();
    CP_WAIT0();
    __syncthreads();

    float cacc[16][4];
    #pragma unroll
    for (int q = 0; q < 16; q++)
        #pragma unroll
        for (int v = 0; v < 4; v++) cacc[q][v] = 0.0f;

    for (int k = 0; k < NCH; k++) {
        const int rbuf = k % 3;

        // prefetch chunk k+2 into ring slot (k+2)%3 — overlaps whole chunk.
        // Safe: slot last read at chunk k-1, all warps past barrier(k-1).
        if (k + 2 < NCH) load_chunk(sb, k + 2, tid);
        CP_COMMIT();

        // ---- GEMM1: S^T[16j x 32i] = U . V^T  (2 passes: Uh, Ul) ----
        const uint32_t vbase = sb + O_V + rbuf * 18432;
        float sacc[4][4];
        #pragma unroll
        for (int q = 0; q < 4; q++)
            #pragma unroll
            for (int v = 0; v < 4; v++) sacc[q][v] = 0.0f;

        #pragma unroll
        for (int kk = 0; kk < 4; kk++) {
            uint32_t b[8];
            ldsm4(b,     vbase + ((i0 + bRow) * RS + kk * 16 + bCol) * 2);
            ldsm4(b + 4, vbase + ((i0 + 16 + bRow) * RS + kk * 16 + bCol) * 2);
            uint32_t ah[4];
            ldsm4(ah, sb + O_UH + ((j0 + aRow) * RS + kk * 16 + aCol) * 2);
            mma_f16(sacc[0], ah, b);     mma_f16(sacc[1], ah, b + 2);
            mma_f16(sacc[2], ah, b + 4); mma_f16(sacc[3], ah, b + 6);
            uint32_t al[4];
            ldsm4(al, sb + O_UL + ((j0 + aRow) * RS + kk * 16 + aCol) * 2);
            mma_f16(sacc[0], al, b);     mma_f16(sacc[1], al, b + 2);
            mma_f16(sacc[2], al, b + 4); mma_f16(sacc[3], al, b + 6);
        }

        // ---- sigmoid + pack C-frags -> GEMM2 A-frags (registers only) ----
        uint32_t pA[2][4];
        #pragma unroll
        for (int h = 0; h < 2; h++) {
            float t00 = sigm(sacc[2*h][0] + bias),   t01 = sigm(sacc[2*h][1] + bias);
            float t02 = sigm(sacc[2*h][2] + bias),   t03 = sigm(sacc[2*h][3] + bias);
            float t10 = sigm(sacc[2*h+1][0] + bias), t11 = sigm(sacc[2*h+1][1] + bias);
            float t12 = sigm(sacc[2*h+1][2] + bias), t13 = sigm(sacc[2*h+1][3] + bias);
            pA[h][0] = f16x2_of(t00, t01);   // (j,   k 0..7)
            pA[h][1] = f16x2_of(t02, t03);   // (j+8, k 0..7)
            pA[h][2] = f16x2_of(t10, t11);   // (j,   k 8..15)
            pA[h][3] = f16x2_of(t12, t13);   // (j+8, k 8..15)
        }

        // ---- GEMM2: C[16j x 128c] += P^T . ET  over this warp's 32-i slice ----
        {
            const uint32_t ebase = sb + O_E + rbuf * 34816;
            #pragma unroll
            for (int kk2 = 0; kk2 < 2; kk2++) {
                const uint32_t koff = (i0 + kk2 * 16 + bCol) * 2;
                #pragma unroll
                for (int ct = 0; ct < 8; ct++) {
                    uint32_t b[4];
                    ldsm4(b, ebase + (ct * 16 + bRow) * (RSE * 2) + koff);
                    mma_f16(cacc[ct * 2],     pA[kk2], b);
                    mma_f16(cacc[ct * 2 + 1], pA[kk2], b + 2);
                }
            }
        }

        CP_WAIT1();          // chunk k+1 resident (this thread's copies)
        __syncthreads();     // ring-slot publish/reuse point
    }

    // ---- cross-ig reduction (smem, reusing ring area) + epilogue ----
    {
        float* red = (float*)smem;              // [16 warps][16j][128c] = 128 KB
        float* mine = red + w * 2048;
        const int jr = lane >> 2;
        const int cb = (lane & 3) * 2;
        #pragma unroll
        for (int ct = 0; ct < 16; ct++) {
            *(float2*)&mine[jr * 128 + ct * 8 + cb]       = make_float2(cacc[ct][0], cacc[ct][1]);
            *(float2*)&mine[(jr + 8) * 128 + ct * 8 + cb] = make_float2(cacc[ct][2], cacc[ct][3]);
        }
        __syncthreads();

        #pragma unroll
        for (int s = 0; s < 16; s++) {
            const int e = tid + s * 512;        // 0..8191
            const int j = e >> 7, c = e & 127;
            const int jgg = j >> 4, jrr = j & 15;
            float p = red[(jgg * 4 + 0) * 2048 + jrr * 128 + c]
                    + red[(jgg * 4 + 1) * 2048 + jrr * 128 + c]
                    + red[(jgg * 4 + 2) * 2048 + jrr * 128 + c]
                    + red[(jgg * 4 + 3) * 2048 + jrr * 128 + c];
            const int jglob = jb + j;
            const int b = c >> 6, d = c & 63;
            const int idx = (b * NT + jglob) * 64 + d;
            out[idx] = states[idx] + p - g_diag[jglob] * g_eff[jglob * 128 + c];
        }
    }
}

// ============================================================================
extern "C" void kernel_launch(void* const* d_in, const int* in_sizes, int n_in,
                              void* d_out, int out_size) {
    const float* states = (const float*)d_in[0];  // [2,8192,64]
    const float* prof   = (const float*)d_in[1];  // [2,8192]
    const float* U      = (const float*)d_in[2];  // [8192,64]
    const float* W      = (const float*)d_in[3];  // [1,64,64]
    const float* bias   = (const float*)d_in[4];  // [1]
    float* out = (float*)d_out;

    cudaFuncSetAttribute(prep_kernel, cudaFuncAttributeMaxDynamicSharedMemorySize, PREP_SMEM);
    prep_kernel<<<NT / 64, 256, PREP_SMEM>>>(states, prof, U, W, bias);

    cudaFuncSetAttribute(main_kernel, cudaFuncAttributeMaxDynamicSharedMemorySize, SMEM_TOTAL);
    main_kernel<<<NT / 64, 512, SMEM_TOTAL>>>(states, bias, out);
}